// round 5
// baseline (speedup 1.0000x reference)
#include <cuda_runtime.h>
#include <cuda_bf16.h>
#include <cstddef>
#include <cstdint>

#define NN 50000
#define EE 800000
#define F_IN 128
#define D1 90
#define LD1 96      // padded row stride: 384B = 3 aligned 128B lines
#define D2 80
#define D3 50
#define NSCAN 49    // ceil(50000/1024)

// ---------------- scratch (static device globals; no allocation) ----------------
__device__ int   g_deg[NN];
__device__ int   g_fill[NN];
__device__ float g_disq[NN];
__device__ int   g_rowptr[NN + 1];
__device__ int2  g_edge[EE];                  // {src, norm-as-int-bits}
__device__ int   g_bsum[64];
__device__ float g_bufA[(size_t)NN * LD1];
__device__ float g_bufB[(size_t)NN * LD1];
__device__ float g_stats[5 * 256];            // 5 slots: [0..D) sum, [128..128+D) sumsq

// ---------------- tf32 mma helpers ----------------
__device__ __forceinline__ uint32_t f2tf32(float f) {
    uint32_t r;
    asm("cvt.rna.tf32.f32 %0, %1;" : "=r"(r) : "f"(f));
    return r;
}

__device__ __forceinline__ void mma_tf32(float& c0, float& c1, float& c2, float& c3,
                                         uint32_t a0, uint32_t a1, uint32_t a2, uint32_t a3,
                                         uint32_t b0, uint32_t b1) {
    asm volatile("mma.sync.aligned.m16n8k8.row.col.f32.tf32.tf32.f32 "
                 "{%0,%1,%2,%3}, {%4,%5,%6,%7}, {%8,%9}, {%0,%1,%2,%3};"
                 : "+f"(c0), "+f"(c1), "+f"(c2), "+f"(c3)
                 : "r"(a0), "r"(a1), "r"(a2), "r"(a3), "r"(b0), "r"(b1));
}

// ---------------- graph build ----------------
__global__ void zero_deg_kernel() {
    int i = blockIdx.x * blockDim.x + threadIdx.x;
    if (i < NN) g_deg[i] = 0;
    if (i < 5 * 256) g_stats[i] = 0.0f;
}

__global__ void count_kernel(const int* __restrict__ dst) {
    int e = blockIdx.x * blockDim.x + threadIdx.x;
    if (e < EE) atomicAdd(&g_deg[dst[e]], 1);
}

// per-block exclusive scan into rowptr; block totals to g_bsum; fused disq + fill-reset
__global__ __launch_bounds__(1024) void scan_local_kernel() {
    __shared__ int s[1024];
    int tid = threadIdx.x;
    int i = blockIdx.x * 1024 + tid;
    int v = (i < NN) ? g_deg[i] : 0;
    if (i < NN) {
        g_disq[i] = rsqrtf((float)(v + 1));
        g_fill[i] = 0;
    }
    s[tid] = v;
    __syncthreads();
    #pragma unroll
    for (int off = 1; off < 1024; off <<= 1) {
        int t = (tid >= off) ? s[tid - off] : 0;
        __syncthreads();
        s[tid] += t;
        __syncthreads();
    }
    if (i < NN) g_rowptr[i] = s[tid] - v;     // block-local exclusive
    if (tid == 1023) g_bsum[blockIdx.x] = s[1023];
}

// merged: per-block offset from g_bsum prefix, then add
__global__ __launch_bounds__(1024) void scan_add_kernel() {
    __shared__ int sb[64];
    __shared__ int soff;
    int tid = threadIdx.x;
    if (tid < 64) sb[tid] = (tid < NSCAN) ? g_bsum[tid] : 0;
    __syncthreads();
    if (tid == 0) {
        int o = 0;
        for (int j = 0; j < blockIdx.x; j++) o += sb[j];
        soff = o;
    }
    __syncthreads();
    int i = blockIdx.x * 1024 + tid;
    if (i < NN) g_rowptr[i] += soff;
    if (i == 0) g_rowptr[NN] = EE;
}

__global__ void fill_kernel(const int* __restrict__ src, const int* __restrict__ dst) {
    int e = blockIdx.x * blockDim.x + threadIdx.x;
    if (e < EE) {
        int d = dst[e];
        int s = src[e];
        int p = g_rowptr[d] + atomicAdd(&g_fill[d], 1);
        float nrm = g_disq[s] * g_disq[d];
        g_edge[p] = make_int2(s, __float_as_int(nrm));
    }
}

// ---------------- 3xTF32 tensor-core GEMM (fp32-equivalent accuracy) ----------------
// Y[N,D] = XF(X)[N,K] @ W[K,D] (+bias) (+stats)
// XF: 0=identity, 1=x*scale+shift (BN from statsIn+g/b), 2=relu(...)
// Each operand split hi/lo; acc += Ah*Bh + Al*Bh + Ah*Bl  (residual O(2^-22)).
template<int K, int LDX, int D, int LDY, int XF, bool BIAS, bool STATS>
__global__ __launch_bounds__(256)
void gemm_tc(const float* __restrict__ X, const float* __restrict__ W,
             const float* __restrict__ Bv,
             const float* __restrict__ bng, const float* __restrict__ bnb,
             const float* __restrict__ statsIn, float* __restrict__ statsOut,
             float* __restrict__ Y, int nrows)
{
    constexpr int KP = (K + 7) & ~7;
    constexpr int NP = (D + 7) & ~7;
    constexpr int WS = NP + 1;          // smem W stride (bank-conflict pad)
    constexpr int NT = NP / 8;

    extern __shared__ float smf[];
    uint32_t* Wh   = (uint32_t*)smf;                 // [KP*WS] tf32 hi bits
    uint32_t* Wl   = Wh + KP * WS;                   // [KP*WS] tf32 lo bits
    float*    ssc  = smf + 2 * KP * WS;              // [KP]
    float*    ssh  = ssc + KP;                       // [KP]
    float*    sbias= ssh + KP;                       // [NP]
    float*    ssum = sbias + NP;                     // [NP]
    float*    ssq  = ssum + NP;                      // [NP]

    int tid = threadIdx.x;
    // stage W (split into tf32 hi/lo), zero padding
    for (int i = tid; i < KP * NP; i += 256) {
        int k = i / NP, n = i % NP;
        float v = (k < K && n < D) ? W[k * D + n] : 0.0f;
        uint32_t hb = f2tf32(v);
        float lo = v - __uint_as_float(hb);
        Wh[k * WS + n] = hb;
        Wl[k * WS + n] = f2tf32(lo);
    }
    if (XF > 0) {
        for (int i = tid; i < KP; i += 256) {
            if (i < K) {
                float mean = statsIn[i] * (1.0f / NN);
                float var  = statsIn[128 + i] * (1.0f / NN) - mean * mean;
                float inv  = rsqrtf(var + 1e-5f);
                float scv  = bng[i] * inv;
                ssc[i] = scv;
                ssh[i] = bnb[i] - mean * scv;
            } else { ssc[i] = 0.0f; ssh[i] = 0.0f; }
        }
    }
    for (int i = tid; i < NP; i += 256) {
        sbias[i] = (BIAS && i < D) ? Bv[i] : 0.0f;
        if (STATS) { ssum[i] = 0.0f; ssq[i] = 0.0f; }
    }
    __syncthreads();

    int lane = tid & 31;
    int wid  = tid >> 5;
    int qr   = lane >> 2;     // 0..7
    int qc   = lane & 3;      // 0..3
    int ra = blockIdx.x * 128 + wid * 16 + qr;
    int rb = ra + 8;
    bool va = ra < nrows, vb = rb < nrows;
    const float* xa = X + (size_t)ra * LDX;
    const float* xb = X + (size_t)rb * LDX;

    float acc[NT][4];
    #pragma unroll
    for (int j = 0; j < NT; j++) { acc[j][0] = acc[j][1] = acc[j][2] = acc[j][3] = 0.0f; }

    for (int k0 = 0; k0 < KP; k0 += 8) {
        int kc = k0 + qc;
        float f0 = va ? xa[kc]     : 0.0f;
        float f1 = vb ? xb[kc]     : 0.0f;
        float f2 = va ? xa[kc + 4] : 0.0f;
        float f3 = vb ? xb[kc + 4] : 0.0f;
        if (XF > 0) {
            float s0 = ssc[kc], h0 = ssh[kc];
            float s1 = ssc[kc + 4], h1 = ssh[kc + 4];
            f0 = f0 * s0 + h0; f1 = f1 * s0 + h0;
            f2 = f2 * s1 + h1; f3 = f3 * s1 + h1;
            if (XF == 2) {
                f0 = fmaxf(f0, 0.0f); f1 = fmaxf(f1, 0.0f);
                f2 = fmaxf(f2, 0.0f); f3 = fmaxf(f3, 0.0f);
            }
        }
        uint32_t a0h = f2tf32(f0), a1h = f2tf32(f1), a2h = f2tf32(f2), a3h = f2tf32(f3);
        uint32_t a0l = f2tf32(f0 - __uint_as_float(a0h));
        uint32_t a1l = f2tf32(f1 - __uint_as_float(a1h));
        uint32_t a2l = f2tf32(f2 - __uint_as_float(a2h));
        uint32_t a3l = f2tf32(f3 - __uint_as_float(a3h));
        const uint32_t* wh0 = Wh + (k0 + qc) * WS + qr;
        const uint32_t* wh1 = wh0 + 4 * WS;
        const uint32_t* wl0 = Wl + (k0 + qc) * WS + qr;
        const uint32_t* wl1 = wl0 + 4 * WS;
        #pragma unroll
        for (int j = 0; j < NT; j++) {
            uint32_t b0h = wh0[j * 8];
            uint32_t b1h = wh1[j * 8];
            uint32_t b0l = wl0[j * 8];
            uint32_t b1l = wl1[j * 8];
            mma_tf32(acc[j][0], acc[j][1], acc[j][2], acc[j][3], a0l, a1l, a2l, a3l, b0h, b1h);
            mma_tf32(acc[j][0], acc[j][1], acc[j][2], acc[j][3], a0h, a1h, a2h, a3h, b0l, b1l);
            mma_tf32(acc[j][0], acc[j][1], acc[j][2], acc[j][3], a0h, a1h, a2h, a3h, b0h, b1h);
        }
    }

    // epilogue: bias, store (float2), stats
    #pragma unroll
    for (int j = 0; j < NT; j++) {
        int c = j * 8 + 2 * qc;
        float b0 = sbias[c], b1 = sbias[c + 1];
        float v0 = acc[j][0] + b0, v1 = acc[j][1] + b1;   // row ra
        float v2 = acc[j][2] + b0, v3 = acc[j][3] + b1;   // row rb
        if (c < LDY) {
            if (va) *(float2*)(Y + (size_t)ra * LDY + c) = make_float2(v0, v1);
            if (vb) *(float2*)(Y + (size_t)rb * LDY + c) = make_float2(v2, v3);
        }
        if (STATS) {
            if (c < D) {
                float s0 = 0.f, q0 = 0.f;
                if (va) { s0 += v0; q0 += v0 * v0; }
                if (vb) { s0 += v2; q0 += v2 * v2; }
                if (s0 != 0.f || q0 != 0.f) { atomicAdd(&ssum[c], s0); atomicAdd(&ssq[c], q0); }
            }
            if (c + 1 < D) {
                float s1 = 0.f, q1 = 0.f;
                if (va) { s1 += v1; q1 += v1 * v1; }
                if (vb) { s1 += v3; q1 += v3 * v3; }
                if (s1 != 0.f || q1 != 0.f) { atomicAdd(&ssum[c + 1], s1); atomicAdd(&ssq[c + 1], q1); }
            }
        }
    }
    if (STATS) {
        __syncthreads();
        for (int i = tid; i < NP; i += 256) {
            if (i < D) {
                atomicAdd(&statsOut[i], ssum[i]);
                atomicAdd(&statsOut[128 + i], ssq[i]);
            }
        }
    }
}

// ---------------- pull aggregation + bias + relu (+stats), float4 lanes ----------------
template<bool STATS>
__global__ __launch_bounds__(256)
void aggregate_kernel(const float* __restrict__ T, const float* __restrict__ Bv,
                      float* __restrict__ Y, float* __restrict__ statsOut)
{
    constexpr int D = D1;
    constexpr int SD = STATS ? D : 1;
    __shared__ float ssum[SD], ssq[SD];
    int tid = threadIdx.x;
    if (STATS) {
        for (int i = tid; i < D; i += 256) { ssum[i] = 0.0f; ssq[i] = 0.0f; }
        __syncthreads();
    }
    int node = blockIdx.x * 8 + (tid >> 5);
    int lane = tid & 31;
    int c0 = lane * 4;
    bool act = (node < NN) && (lane < 24);
    float vals[4] = {0.0f, 0.0f, 0.0f, 0.0f};

    if (act) {
        float dsq = g_disq[node];
        float selfw = dsq * dsq;
        float4 t0 = *(const float4*)(T + (size_t)node * LD1 + c0);
        float4 acc = make_float4(t0.x * selfw, t0.y * selfw, t0.z * selfw, t0.w * selfw);

        int beg = g_rowptr[node];
        int end = g_rowptr[node + 1];
        int e = beg;
        for (; e + 2 <= end; e += 2) {
            int2 e0 = g_edge[e];
            int2 e1 = g_edge[e + 1];
            float4 ta = *(const float4*)(T + (size_t)e0.x * LD1 + c0);
            float4 tb = *(const float4*)(T + (size_t)e1.x * LD1 + c0);
            float w0 = __int_as_float(e0.y);
            float w1 = __int_as_float(e1.y);
            acc.x += w0 * ta.x; acc.y += w0 * ta.y; acc.z += w0 * ta.z; acc.w += w0 * ta.w;
            acc.x += w1 * tb.x; acc.y += w1 * tb.y; acc.z += w1 * tb.z; acc.w += w1 * tb.w;
        }
        if (e < end) {
            int2 e0 = g_edge[e];
            float4 ta = *(const float4*)(T + (size_t)e0.x * LD1 + c0);
            float w0 = __int_as_float(e0.y);
            acc.x += w0 * ta.x; acc.y += w0 * ta.y; acc.z += w0 * ta.z; acc.w += w0 * ta.w;
        }
        float am[4] = {acc.x, acc.y, acc.z, acc.w};
        #pragma unroll
        for (int m = 0; m < 4; m++) {
            int c = c0 + m;
            vals[m] = (c < D) ? fmaxf(am[m] + Bv[c], 0.0f) : 0.0f;
        }
        *(float4*)(Y + (size_t)node * LD1 + c0) = make_float4(vals[0], vals[1], vals[2], vals[3]);
    }
    if (STATS) {
        #pragma unroll
        for (int m = 0; m < 4; m++) {
            int c = c0 + m;
            if (act && c < D) {
                atomicAdd(&ssum[c], vals[m]);
                atomicAdd(&ssq[c], vals[m] * vals[m]);
            }
        }
        __syncthreads();
        if (tid < D) {
            atomicAdd(&statsOut[tid], ssum[tid]);
            atomicAdd(&statsOut[128 + tid], ssq[tid]);
        }
    }
}

// ---------------- final fc3: out = relu(bn3(x)) @ w + b, bn inline ----------------
__global__ __launch_bounds__(256)
void fc3_kernel(const float* __restrict__ Y, const float* __restrict__ W,
                const float* __restrict__ Bv,
                const float* __restrict__ bng, const float* __restrict__ bnb,
                const float* __restrict__ statsIn, float* __restrict__ out)
{
    __shared__ float sc[D3], sh[D3], sw[D3];
    int tid = threadIdx.x;
    if (tid < D3) {
        float mean = statsIn[tid] * (1.0f / NN);
        float var  = statsIn[128 + tid] * (1.0f / NN) - mean * mean;
        float inv  = rsqrtf(var + 1e-5f);
        float scv  = bng[tid] * inv;
        sc[tid] = scv;
        sh[tid] = bnb[tid] - mean * scv;
        sw[tid] = W[tid];
    }
    __syncthreads();
    int node = blockIdx.x * 8 + (tid >> 5);
    if (node >= NN) return;
    int lane = tid & 31;
    float s = 0.0f;
    if (lane < D3) {
        float v = Y[(size_t)node * D3 + lane];
        v = fmaxf(v * sc[lane] + sh[lane], 0.0f);
        s = v * sw[lane];
    }
    if (lane + 32 < D3) {
        int c = lane + 32;
        float v = Y[(size_t)node * D3 + c];
        v = fmaxf(v * sc[c] + sh[c], 0.0f);
        s += v * sw[c];
    }
    #pragma unroll
    for (int off = 16; off; off >>= 1) s += __shfl_down_sync(0xffffffffu, s, off);
    if (lane == 0) out[node] = s + Bv[0];
}

// smem bytes for gemm_tc<K,.,D,...> (hi+lo W copies)
static int gemm_smem(int K, int D) {
    int KP = (K + 7) & ~7, NP = (D + 7) & ~7;
    return (2 * KP * (NP + 1) + 2 * KP + 3 * NP) * 4;
}

// ---------------- launcher ----------------
extern "C" void kernel_launch(void* const* d_in, const int* in_sizes, int n_in,
                              void* d_out, int out_size)
{
    const float* x       = (const float*)d_in[0];
    const int*   ei      = (const int*)  d_in[1];
    const int*   src     = ei;
    const int*   dst     = ei + EE;
    const float* conv1_w = (const float*)d_in[2];
    const float* conv1_b = (const float*)d_in[3];
    const float* convs_w = (const float*)d_in[4];
    const float* convs_b = (const float*)d_in[5];
    const float* bn1_g   = (const float*)d_in[6];
    const float* bn1_b   = (const float*)d_in[7];
    const float* fc1_w   = (const float*)d_in[8];
    const float* fc1_b   = (const float*)d_in[9];
    const float* bn2_g   = (const float*)d_in[10];
    const float* bn2_b   = (const float*)d_in[11];
    const float* fc2_w   = (const float*)d_in[12];
    const float* fc2_b   = (const float*)d_in[13];
    const float* bn3_g   = (const float*)d_in[14];
    const float* bn3_b   = (const float*)d_in[15];
    const float* fc3_w   = (const float*)d_in[16];
    const float* fc3_b   = (const float*)d_in[17];
    float* out = (float*)d_out;

    float *bufA = nullptr, *bufB = nullptr, *stats = nullptr;
    cudaGetSymbolAddress((void**)&bufA, g_bufA);
    cudaGetSymbolAddress((void**)&bufB, g_bufB);
    cudaGetSymbolAddress((void**)&stats, g_stats);

    static cudaStream_t s2 = nullptr;
    static cudaEvent_t  evFork = nullptr, evJoin = nullptr;
    if (!s2) {
        cudaStreamCreateWithFlags(&s2, cudaStreamNonBlocking);
        cudaEventCreateWithFlags(&evFork, cudaEventDisableTiming);
        cudaEventCreateWithFlags(&evJoin, cudaEventDisableTiming);
        cudaFuncSetAttribute(gemm_tc<F_IN, F_IN, D1, LD1, 0, false, false>,
                             cudaFuncAttributeMaxDynamicSharedMemorySize, 112 * 1024);
        cudaFuncSetAttribute(gemm_tc<D1, LD1, D1, LD1, 0, false, false>,
                             cudaFuncAttributeMaxDynamicSharedMemorySize, 90 * 1024);
        cudaFuncSetAttribute(gemm_tc<D1, LD1, D1, LD1, 1, false, false>,
                             cudaFuncAttributeMaxDynamicSharedMemorySize, 90 * 1024);
        cudaFuncSetAttribute(gemm_tc<D1, LD1, D2, D2, 1, true, true>,
                             cudaFuncAttributeMaxDynamicSharedMemorySize, 80 * 1024);
        cudaFuncSetAttribute(gemm_tc<D2, D2, D3, D3, 2, true, true>,
                             cudaFuncAttributeMaxDynamicSharedMemorySize, 64 * 1024);
    }

    const int TB = 256;
    const int gN = (NN + TB - 1) / TB;
    const int gE = (EE + TB - 1) / TB;
    const int gNode8 = (NN + 7) / 8;
    const int gGemm  = (NN + 127) / 128;

    const int sm_conv1 = gemm_smem(F_IN, D1);
    const int sm_conv  = gemm_smem(D1, D1);
    const int sm_fc1   = gemm_smem(D1, D2);
    const int sm_fc2   = gemm_smem(D2, D3);

    // ---- fork: conv1 dense transform overlaps graph build ----
    cudaEventRecord(evFork, 0);
    cudaStreamWaitEvent(s2, evFork, 0);
    gemm_tc<F_IN, F_IN, D1, LD1, 0, false, false><<<gGemm, TB, sm_conv1, s2>>>(
        x, conv1_w, nullptr, nullptr, nullptr, nullptr, nullptr, bufA, NN);
    cudaEventRecord(evJoin, s2);

    // ---- graph build ----
    zero_deg_kernel<<<gN, TB>>>();
    count_kernel<<<gE, TB>>>(dst);
    scan_local_kernel<<<NSCAN, 1024>>>();
    scan_add_kernel<<<NSCAN, 1024>>>();
    fill_kernel<<<gE, TB>>>(src, dst);

    // ---- join, aggregate conv1 ----
    cudaStreamWaitEvent(0, evJoin, 0);
    aggregate_kernel<false><<<gNode8, TB>>>(bufA, conv1_b, bufB, nullptr);

    // ---- conv2 (no BN on input), stats -> slot0 ----
    gemm_tc<D1, LD1, D1, LD1, 0, false, false><<<gGemm, TB, sm_conv>>>(
        bufB, convs_w, nullptr, nullptr, nullptr, nullptr, nullptr, bufA, NN);
    aggregate_kernel<true><<<gNode8, TB>>>(bufA, convs_b, bufB, stats + 0 * 256);

    // ---- conv3 (BN slot0 on input), stats -> slot1 ----
    gemm_tc<D1, LD1, D1, LD1, 1, false, false><<<gGemm, TB, sm_conv>>>(
        bufB, convs_w + (size_t)1 * D1 * D1, nullptr, bn1_g, bn1_b, stats + 0 * 256, nullptr, bufA, NN);
    aggregate_kernel<true><<<gNode8, TB>>>(bufA, convs_b + 1 * D1, bufB, stats + 1 * 256);

    // ---- conv4 (BN slot1 on input), stats -> slot2 ----
    gemm_tc<D1, LD1, D1, LD1, 1, false, false><<<gGemm, TB, sm_conv>>>(
        bufB, convs_w + (size_t)2 * D1 * D1, nullptr, bn1_g, bn1_b, stats + 1 * 256, nullptr, bufA, NN);
    aggregate_kernel<true><<<gNode8, TB>>>(bufA, convs_b + 2 * D1, bufB, stats + 2 * 256);

    // ---- fc1 (BN slot2 input) + bias + stats -> slot3 ----
    gemm_tc<D1, LD1, D2, D2, 1, true, true><<<gGemm, TB, sm_fc1>>>(
        bufB, fc1_w, fc1_b, bn1_g, bn1_b, stats + 2 * 256, stats + 3 * 256, bufA, NN);

    // ---- fc2 (relu(BN slot3) input) + bias + stats -> slot4 ----
    gemm_tc<D2, D2, D3, D3, 2, true, true><<<gGemm, TB, sm_fc2>>>(
        bufA, fc2_w, fc2_b, bn2_g, bn2_b, stats + 3 * 256, stats + 4 * 256, bufB, NN);

    // ---- fc3 (relu(BN slot4) input, inline) ----
    fc3_kernel<<<gNode8, TB>>>(bufB, fc3_w, fc3_b, bn3_g, bn3_b, stats + 4 * 256, out);
}